// round 1
// baseline (speedup 1.0000x reference)
#include <cuda_runtime.h>
#include <math.h>

#define VOCAB1 50001
#define NEMB   256
#define NSEQ   64
#define NFEAT  512
#define NBATCH 1024
#define NROWS  2048   // both sequences stacked

// Scratch: projected embedding table EW = embedding @ W  (~102 MB)
__device__ float g_EW[(size_t)VOCAB1 * NFEAT];

// ---------------- packed f32x2 helpers (sm_100a) ----------------
__device__ __forceinline__ unsigned long long pk2(float lo, float hi) {
    unsigned long long r;
    asm("mov.b64 %0, {%1, %2};" : "=l"(r) : "f"(lo), "f"(hi));
    return r;
}
__device__ __forceinline__ void upk2(unsigned long long v, float &lo, float &hi) {
    asm("mov.b64 {%0, %1}, %2;" : "=f"(lo), "=f"(hi) : "l"(v));
}
__device__ __forceinline__ unsigned long long fma2(unsigned long long a,
                                                   unsigned long long b,
                                                   unsigned long long c) {
    unsigned long long d;
    asm("fma.rn.f32x2 %0, %1, %2, %3;" : "=l"(d) : "l"(a), "l"(b), "l"(c));
    return d;
}

// ---------------- Kernel 1: EW = embedding @ W  ([50001,256]x[256,512]) ----
// 64x64 tile, 256 threads, 4x4 per thread, f32x2 accumulation over col pairs.
__global__ __launch_bounds__(256, 1) void ew_kernel(const float* __restrict__ emb,
                                                    const float* __restrict__ W)
{
    __shared__ __align__(16) float As[16][64];   // [k][m]
    __shared__ __align__(16) float Bs[16][64];   // [k][n]
    const int bm = blockIdx.y * 64;
    const int bn = blockIdx.x * 64;
    const int tid = threadIdx.x;
    const int tx = tid & 15;
    const int ty = tid >> 4;
    const int m0 = ty * 4;
    const int n0 = tx * 4;

    const int lmA = tid >> 2;        // 0..63 : row within tile
    const int lkA = (tid & 3) * 4;   // 0,4,8,12 : k offset
    const int lkB = tid >> 4;        // 0..15 : k row for B
    const int lnB = (tid & 15) * 4;  // col offset for B

    unsigned long long acc[4][2];
#pragma unroll
    for (int i = 0; i < 4; i++) { acc[i][0] = 0ull; acc[i][1] = 0ull; }

    const int growA = bm + lmA;
    for (int k0 = 0; k0 < NEMB; k0 += 16) {
        float4 av = make_float4(0.f, 0.f, 0.f, 0.f);
        if (growA < VOCAB1)
            av = *(const float4*)(emb + (size_t)growA * NEMB + k0 + lkA);
        float4 bv = *(const float4*)(W + (size_t)(k0 + lkB) * NFEAT + bn + lnB);
        __syncthreads();
        As[lkA + 0][lmA] = av.x;
        As[lkA + 1][lmA] = av.y;
        As[lkA + 2][lmA] = av.z;
        As[lkA + 3][lmA] = av.w;
        *(float4*)&Bs[lkB][lnB] = bv;
        __syncthreads();
#pragma unroll
        for (int k = 0; k < 16; k++) {
            unsigned long long b01 = *(const unsigned long long*)&Bs[k][n0];
            unsigned long long b23 = *(const unsigned long long*)&Bs[k][n0 + 2];
#pragma unroll
            for (int i = 0; i < 4; i++) {
                float a = As[k][m0 + i];
                unsigned long long ad = pk2(a, a);
                acc[i][0] = fma2(ad, b01, acc[i][0]);
                acc[i][1] = fma2(ad, b23, acc[i][1]);
            }
        }
    }
#pragma unroll
    for (int i = 0; i < 4; i++) {
        int row = bm + m0 + i;
        if (row < VOCAB1) {
            float c0, c1, c2, c3;
            upk2(acc[i][0], c0, c1);
            upk2(acc[i][1], c2, c3);
            *(float4*)(g_EW + (size_t)row * NFEAT + bn + n0) = make_float4(c0, c1, c2, c3);
        }
    }
}

// ---------------- Kernel 2: recurrent scan -------------------------------
// 128 CTAs x 16 rows. h kept transposed in SMEM as h_s[feat][row] (pad 18 so
// row-pairs stay 8B-aligned + broadcast reads are conflict-free).
// Each thread owns 2 adjacent output features (j0, j0+1) for all 16 rows.
// Accumulators packed over row pairs -> fma.rn.f32x2, dup cost only on U.
__global__ __launch_bounds__(256, 1) void rnn_kernel(
    const int*  __restrict__ ids1,
    const int*  __restrict__ ids2,
    const float* __restrict__ U,
    const float* __restrict__ bias,
    float* __restrict__ out)
{
    __shared__ __align__(16) float h_s[NFEAT * 18];
    __shared__ int s_id[16];

    const int tid = threadIdx.x;
    const int rb0 = blockIdx.x * 16;               // global row base (0..2032)
    const int j0  = tid * 2;                       // my feature pair
    const float bj0 = bias[j0];
    const float bj1 = bias[j0 + 1];
    const int* myids = (rb0 < NBATCH) ? ids1 : ids2;
    const int rbase  = rb0 & (NBATCH - 1);

    for (int i = tid; i < NFEAT * 18; i += 256) h_s[i] = 0.f;

    unsigned long long acc[8][2];

    for (int t = 0; t < NSEQ; t++) {
        if (tid < 16) s_id[tid] = myids[(rbase + tid) * NSEQ + t];
        __syncthreads();   // s_id ready + prev-step h writes visible

        // init accumulators with gathered input projection EW[id]
#pragma unroll
        for (int rp = 0; rp < 8; rp++) {
            const float* e0 = g_EW + (size_t)s_id[2 * rp]     * NFEAT + j0;
            const float* e1 = g_EW + (size_t)s_id[2 * rp + 1] * NFEAT + j0;
            float2 x0 = *(const float2*)e0;
            float2 x1 = *(const float2*)e1;
            acc[rp][0] = pk2(x0.x, x1.x);
            acc[rp][1] = pk2(x0.y, x1.y);
        }

        // h @ U : stream U rows from L2, h row-pairs from SMEM (broadcast)
#pragma unroll 4
        for (int k = 0; k < NFEAT; k++) {
            float2 uv = *(const float2*)(U + (size_t)k * NFEAT + j0);
            unsigned long long u0 = pk2(uv.x, uv.x);
            unsigned long long u1 = pk2(uv.y, uv.y);
            const float* hrow = h_s + k * 18;
#pragma unroll
            for (int rp = 0; rp < 8; rp++) {
                unsigned long long hp = *(const unsigned long long*)(hrow + 2 * rp);
                acc[rp][0] = fma2(u0, hp, acc[rp][0]);
                acc[rp][1] = fma2(u1, hp, acc[rp][1]);
            }
        }

        // epilogue: bias + tanh + mask-select against old h
#pragma unroll
        for (int rp = 0; rp < 8; rp++) {
            bool m0 = (s_id[2 * rp]     != 0);
            bool m1 = (s_id[2 * rp + 1] != 0);
#pragma unroll
            for (int c = 0; c < 2; c++) {
                float lo, hi;
                upk2(acc[rp][c], lo, hi);
                float bb = c ? bj1 : bj0;
                float n0 = tanhf(lo + bb);
                float n1 = tanhf(hi + bb);
                float o0 = m0 ? n0 : h_s[(j0 + c) * 18 + 2 * rp];
                float o1 = m1 ? n1 : h_s[(j0 + c) * 18 + 2 * rp + 1];
                acc[rp][c] = pk2(o0, o1);   // reuse acc as new-h staging
            }
        }
        __syncthreads();   // all reads of old h done
#pragma unroll
        for (int rp = 0; rp < 8; rp++) {
            *(unsigned long long*)(h_s + (j0 + 0) * 18 + 2 * rp) = acc[rp][0];
            *(unsigned long long*)(h_s + (j0 + 1) * 18 + 2 * rp) = acc[rp][1];
        }
    }

    // final states live in acc -> write straight to out (rows 0..2047 map
    // contiguously onto state1 then state2)
#pragma unroll
    for (int rp = 0; rp < 8; rp++) {
#pragma unroll
        for (int c = 0; c < 2; c++) {
            float o0, o1;
            upk2(acc[rp][c], o0, o1);
            out[(size_t)(rb0 + 2 * rp)     * NFEAT + j0 + c] = o0;
            out[(size_t)(rb0 + 2 * rp + 1) * NFEAT + j0 + c] = o1;
        }
    }
}

// ---------------- Kernel 3: cosine similarity ----------------------------
__global__ __launch_bounds__(256) void sim_kernel(float* __restrict__ out)
{
    const int b    = blockIdx.x * 8 + (threadIdx.x >> 5);
    const int lane = threadIdx.x & 31;
    const float* s1 = out + (size_t)b * NFEAT;
    const float* s2 = out + (size_t)(NBATCH + b) * NFEAT;
    float dot = 0.f, q1 = 0.f, q2 = 0.f;
    for (int j = lane; j < NFEAT; j += 32) {
        float a = s1[j], c = s2[j];
        dot += a * c;
        q1  += a * a;
        q2  += c * c;
    }
#pragma unroll
    for (int o = 16; o > 0; o >>= 1) {
        dot += __shfl_xor_sync(0xffffffffu, dot, o);
        q1  += __shfl_xor_sync(0xffffffffu, q1,  o);
        q2  += __shfl_xor_sync(0xffffffffu, q2,  o);
    }
    if (lane == 0) {
        float n1 = sqrtf(fmaxf(q1, 1e-12f));
        float n2 = sqrtf(fmaxf(q2, 1e-12f));
        out[(size_t)NROWS * NFEAT + b] = dot / (n1 * n2);
    }
}

// ---------------- launch --------------------------------------------------
extern "C" void kernel_launch(void* const* d_in, const int* in_sizes, int n_in,
                              void* d_out, int out_size)
{
    (void)in_sizes; (void)n_in; (void)out_size;
    const int*   ids1 = (const int*)  d_in[0];
    const int*   ids2 = (const int*)  d_in[1];
    const float* emb  = (const float*)d_in[2];
    const float* W    = (const float*)d_in[3];
    const float* U    = (const float*)d_in[4];
    const float* bias = (const float*)d_in[5];
    float* out = (float*)d_out;

    dim3 g1(NFEAT / 64, (VOCAB1 + 63) / 64);   // 8 x 782
    ew_kernel<<<g1, 256>>>(emb, W);
    rnn_kernel<<<NROWS / 16, 256>>>(ids1, ids2, U, bias, out);
    sim_kernel<<<NBATCH / 8, 256>>>(out);
}

// round 4
// speedup vs baseline: 1.5854x; 1.5854x over previous
#include <cuda_runtime.h>
#include <math.h>

#define VOCAB1 50001
#define NEMB   256
#define NSEQ   64
#define NFEAT  512
#define NBATCH 1024
#define NROWS  2048

#define KCHUNK 32
#define NCHUNK 16                       // chunks per timestep (512/32)
#define UCHUNK_FLOATS (KCHUNK * NFEAT)  // 16384 floats = 64 KB
#define UCHUNK_BYTES  (UCHUNK_FLOATS * 4)

// smem layout (floats): [0:4) mbarriers (2 x u64), [4:20) s_id, pad to 32,
// [32 : 32+2*16384) U double buffer, then h state 512 x 20.
#define SM_MBAR 0
#define SM_SID  4
#define SM_U    32
#define SM_H    (SM_U + 2 * UCHUNK_FLOATS)          // 32800
#define SM_TOTAL_FLOATS (SM_H + NFEAT * 20)         // 43040
#define SM_TOTAL_BYTES  (SM_TOTAL_FLOATS * 4)       // 172160

typedef unsigned long long ull;

// Scratch: projected embedding table EW = embedding @ W  (~102 MB)
__device__ float g_EW[(size_t)VOCAB1 * NFEAT];

// ---------------- packed f32x2 helpers ----------------
__device__ __forceinline__ ull pk2(float lo, float hi) {
    ull r;
    asm("mov.b64 %0, {%1, %2};" : "=l"(r) : "f"(lo), "f"(hi));
    return r;
}
__device__ __forceinline__ void upk2(ull v, float &lo, float &hi) {
    asm("mov.b64 {%0, %1}, %2;" : "=f"(lo), "=f"(hi) : "l"(v));
}
__device__ __forceinline__ ull fma2(ull a, ull b, ull c) {
    ull d;
    asm("fma.rn.f32x2 %0, %1, %2, %3;" : "=l"(d) : "l"(a), "l"(b), "l"(c));
    return d;
}

// ---------------- mbarrier / bulk-async helpers ----------------
__device__ __forceinline__ unsigned smem_u32(const void* p) {
    unsigned a;
    asm("{ .reg .u64 t; cvta.to.shared.u64 t, %1; cvt.u32.u64 %0, t; }"
        : "=r"(a) : "l"(p));
    return a;
}
__device__ __forceinline__ void mbar_init(unsigned a, unsigned cnt) {
    asm volatile("mbarrier.init.shared.b64 [%0], %1;" :: "r"(a), "r"(cnt) : "memory");
}
__device__ __forceinline__ void mbar_wait(unsigned a, unsigned par) {
    asm volatile(
        "{\n\t.reg .pred P;\n\t"
        "WL_%=:\n\t"
        "mbarrier.try_wait.parity.acquire.cta.shared::cta.b64 P, [%0], %1, 0x989680;\n\t"
        "@!P bra WL_%=;\n\t}"
        :: "r"(a), "r"(par) : "memory");
}
__device__ __forceinline__ void bulk_load(unsigned dst, const void* src,
                                          unsigned bytes, unsigned mbar) {
    asm volatile("mbarrier.arrive.expect_tx.shared.b64 _, [%0], %1;"
                 :: "r"(mbar), "r"(bytes) : "memory");
    asm volatile(
        "cp.async.bulk.shared::cta.global.mbarrier::complete_tx::bytes [%0], [%1], %2, [%3];"
        :: "r"(dst), "l"(src), "r"(bytes), "r"(mbar) : "memory");
}

// ---------------- Kernel 1: EW = embedding @ W --------------------------
// 128x128 tile, 256 threads, 8x8 per thread, f32x2 over col pairs.
__global__ __launch_bounds__(256) void ew_kernel(const float* __restrict__ emb,
                                                 const float* __restrict__ W)
{
    __shared__ __align__(16) float As[16][128];   // [k][m]
    __shared__ __align__(16) float Bs[16][128];   // [k][n]
    const int bm = blockIdx.y * 128;
    const int bn = blockIdx.x * 128;
    const int tid = threadIdx.x;
    const int tx = tid & 15;
    const int ty = tid >> 4;
    const int m0 = ty * 8;
    const int n0 = tx * 8;

    const int lrA = tid >> 1;          // 0..127 A row
    const int lkA = (tid & 1) * 8;     // 0 or 8
    const int lkB = ty;                // 0..15
    const int lnB = tx * 8;

    ull acc[8][4];
#pragma unroll
    for (int i = 0; i < 8; i++)
#pragma unroll
        for (int j = 0; j < 4; j++) acc[i][j] = 0ull;

    const int growA = bm + lrA;
    const bool vA = (growA < VOCAB1);

    for (int k0 = 0; k0 < NEMB; k0 += 16) {
        float4 a0 = make_float4(0.f, 0.f, 0.f, 0.f), a1 = a0;
        if (vA) {
            a0 = *(const float4*)(emb + (size_t)growA * NEMB + k0 + lkA);
            a1 = *(const float4*)(emb + (size_t)growA * NEMB + k0 + lkA + 4);
        }
        float4 b0 = *(const float4*)(W + (size_t)(k0 + lkB) * NFEAT + bn + lnB);
        float4 b1 = *(const float4*)(W + (size_t)(k0 + lkB) * NFEAT + bn + lnB + 4);
        __syncthreads();
        As[lkA + 0][lrA] = a0.x; As[lkA + 1][lrA] = a0.y;
        As[lkA + 2][lrA] = a0.z; As[lkA + 3][lrA] = a0.w;
        As[lkA + 4][lrA] = a1.x; As[lkA + 5][lrA] = a1.y;
        As[lkA + 6][lrA] = a1.z; As[lkA + 7][lrA] = a1.w;
        *(float4*)&Bs[lkB][lnB]     = b0;
        *(float4*)&Bs[lkB][lnB + 4] = b1;
        __syncthreads();
#pragma unroll
        for (int k = 0; k < 16; k++) {
            float4 A0 = *(const float4*)&As[k][m0];
            float4 A1 = *(const float4*)&As[k][m0 + 4];
            longlong2 B0 = *(const longlong2*)&Bs[k][n0];
            longlong2 B1 = *(const longlong2*)&Bs[k][n0 + 4];
            ull b01 = (ull)B0.x, b23 = (ull)B0.y, b45 = (ull)B1.x, b67 = (ull)B1.y;
            float av[8] = {A0.x, A0.y, A0.z, A0.w, A1.x, A1.y, A1.z, A1.w};
#pragma unroll
            for (int i = 0; i < 8; i++) {
                ull ad = pk2(av[i], av[i]);
                acc[i][0] = fma2(ad, b01, acc[i][0]);
                acc[i][1] = fma2(ad, b23, acc[i][1]);
                acc[i][2] = fma2(ad, b45, acc[i][2]);
                acc[i][3] = fma2(ad, b67, acc[i][3]);
            }
        }
    }
#pragma unroll
    for (int i = 0; i < 8; i++) {
        int row = bm + m0 + i;
        if (row < VOCAB1) {
            float c0, c1, c2, c3, c4, c5, c6, c7;
            upk2(acc[i][0], c0, c1); upk2(acc[i][1], c2, c3);
            upk2(acc[i][2], c4, c5); upk2(acc[i][3], c6, c7);
            *(float4*)(g_EW + (size_t)row * NFEAT + bn + n0)     = make_float4(c0, c1, c2, c3);
            *(float4*)(g_EW + (size_t)row * NFEAT + bn + n0 + 4) = make_float4(c4, c5, c6, c7);
        }
    }
}

// ---------------- Kernel 2: recurrent scan ------------------------------
// 128 CTAs x 16 rows, 256 threads. U streamed via cp.async.bulk double
// buffer (2 x 64KB). Thread t: row group g = t>>7 (rows g*8..g*8+7),
// features j0 = (t&127)*4 .. j0+3. h in SMEM transposed [feat][row], pad 20.
__global__ __launch_bounds__(256, 1) void rnn_kernel(
    const int*  __restrict__ ids1,
    const int*  __restrict__ ids2,
    const float* __restrict__ U,
    const float* __restrict__ bias,
    float* __restrict__ out)
{
    extern __shared__ float sm[];
    float* U_s  = sm + SM_U;
    float* h_s  = sm + SM_H;
    int*   s_id = (int*)(sm + SM_SID);
    const unsigned smb  = smem_u32(sm);
    const unsigned mb0  = smb + SM_MBAR * 4;
    const unsigned mb1  = mb0 + 8;
    const unsigned u0a  = smb + SM_U * 4;
    const unsigned u1a  = u0a + UCHUNK_BYTES;

    const int tid = threadIdx.x;
    const int rb0 = blockIdx.x * 16;
    const int g   = tid >> 7;
    const int r0  = g * 8;
    const int j0  = (tid & 127) * 4;
    const int* myids = (rb0 < NBATCH) ? ids1 : ids2;
    const int rbase  = rb0 & (NBATCH - 1);
    const float4 bv = *(const float4*)(bias + j0);

    if (tid == 0) { mbar_init(mb0, 1); mbar_init(mb1, 1); }
    for (int i = tid; i < NFEAT * 20; i += 256) h_s[i] = 0.f;
    if (tid < 16) s_id[tid] = myids[(rbase + tid) * NSEQ + 0];
    __syncthreads();
    if (tid == 0) {
        bulk_load(u0a, U,                 UCHUNK_BYTES, mb0);
        bulk_load(u1a, U + UCHUNK_FLOATS, UCHUNK_BYTES, mb1);
    }

    ull acc[4][4];           // [feat][rowpair]
    unsigned ph0 = 0, ph1 = 0;

    for (int t = 0; t < NSEQ; t++) {
        // init accumulators from EW[id] gather (latency hidden by chunk-0 wait)
#pragma unroll
        for (int rp = 0; rp < 4; rp++) {
            const int i0 = s_id[r0 + 2 * rp];
            const int i1 = s_id[r0 + 2 * rp + 1];
            float4 e0 = *(const float4*)(g_EW + (size_t)i0 * NFEAT + j0);
            float4 e1 = *(const float4*)(g_EW + (size_t)i1 * NFEAT + j0);
            acc[0][rp] = pk2(e0.x, e1.x);
            acc[1][rp] = pk2(e0.y, e1.y);
            acc[2][rp] = pk2(e0.z, e1.z);
            acc[3][rp] = pk2(e0.w, e1.w);
        }

        // 16 k-chunks, buffers alternate even/odd
#pragma unroll 1
        for (int c2 = 0; c2 < 8; c2++) {
#pragma unroll
            for (int half = 0; half < 2; half++) {
                const int c = c2 * 2 + half;
                const unsigned mb = half ? mb1 : mb0;
                if (half) { mbar_wait(mb1, ph1); ph1 ^= 1; }
                else      { mbar_wait(mb0, ph0); ph0 ^= 1; }
                const float* Ub = U_s + half * UCHUNK_FLOATS;
                const float* hp = h_s + (c * KCHUNK) * 20 + r0;
#pragma unroll 8
                for (int kk = 0; kk < KCHUNK; kk++) {
                    float4 uv = *(const float4*)(Ub + kk * NFEAT + j0);
                    longlong2 hA = *(const longlong2*)(hp + kk * 20);
                    longlong2 hB = *(const longlong2*)(hp + kk * 20 + 4);
                    ull hv0 = (ull)hA.x, hv1 = (ull)hA.y;
                    ull hv2 = (ull)hB.x, hv3 = (ull)hB.y;
                    ull ux = pk2(uv.x, uv.x);
                    ull uy = pk2(uv.y, uv.y);
                    ull uz = pk2(uv.z, uv.z);
                    ull uw = pk2(uv.w, uv.w);
                    acc[0][0] = fma2(ux, hv0, acc[0][0]);
                    acc[1][0] = fma2(uy, hv0, acc[1][0]);
                    acc[2][0] = fma2(uz, hv0, acc[2][0]);
                    acc[3][0] = fma2(uw, hv0, acc[3][0]);
                    acc[0][1] = fma2(ux, hv1, acc[0][1]);
                    acc[1][1] = fma2(uy, hv1, acc[1][1]);
                    acc[2][1] = fma2(uz, hv1, acc[2][1]);
                    acc[3][1] = fma2(uw, hv1, acc[3][1]);
                    acc[0][2] = fma2(ux, hv2, acc[0][2]);
                    acc[1][2] = fma2(uy, hv2, acc[1][2]);
                    acc[2][2] = fma2(uz, hv2, acc[2][2]);
                    acc[3][2] = fma2(uw, hv2, acc[3][2]);
                    acc[0][3] = fma2(ux, hv3, acc[0][3]);
                    acc[1][3] = fma2(uy, hv3, acc[1][3]);
                    acc[2][3] = fma2(uz, hv3, acc[2][3]);
                    acc[3][3] = fma2(uw, hv3, acc[3][3]);
                }
                __syncthreads();   // everyone done with this U buffer
                if (tid == 0) {
                    const int gc = t * NCHUNK + c;
                    const int nc = gc + 2;
                    if (nc < NSEQ * NCHUNK) {
                        const float* src = U + (size_t)(nc & 15) * UCHUNK_FLOATS;
                        bulk_load(half ? u1a : u0a, src, UCHUNK_BYTES, mb);
                    }
                }
            }
        }

        // epilogue: bias + tanh + mask select vs old h
#pragma unroll
        for (int rp = 0; rp < 4; rp++) {
            const int row0 = r0 + 2 * rp;
            const bool m0 = (s_id[row0]     != 0);
            const bool m1 = (s_id[row0 + 1] != 0);
            const float bb[4] = {bv.x, bv.y, bv.z, bv.w};
#pragma unroll
            for (int f = 0; f < 4; f++) {
                float lo, hi;
                upk2(acc[f][rp], lo, hi);
                float n0 = tanhf(lo + bb[f]);
                float n1 = tanhf(hi + bb[f]);
                float o0 = m0 ? n0 : h_s[(j0 + f) * 20 + row0];
                float o1 = m1 ? n1 : h_s[(j0 + f) * 20 + row0 + 1];
                acc[f][rp] = pk2(o0, o1);
            }
        }
        __syncthreads();   // all reads of old h + old s_id done
#pragma unroll
        for (int f = 0; f < 4; f++)
#pragma unroll
            for (int rp = 0; rp < 4; rp++)
                *(ull*)(h_s + (j0 + f) * 20 + r0 + 2 * rp) = acc[f][rp];
        if (t + 1 < NSEQ && tid < 16)
            s_id[tid] = myids[(rbase + tid) * NSEQ + t + 1];
        __syncthreads();   // new h + new ids visible
    }

    // final states live in acc
#pragma unroll
    for (int rp = 0; rp < 4; rp++) {
#pragma unroll
        for (int f = 0; f < 4; f++) {
            float o0, o1;
            upk2(acc[f][rp], o0, o1);
            out[(size_t)(rb0 + r0 + 2 * rp)     * NFEAT + j0 + f] = o0;
            out[(size_t)(rb0 + r0 + 2 * rp + 1) * NFEAT + j0 + f] = o1;
        }
    }
}

// ---------------- Kernel 3: cosine similarity ---------------------------
__global__ __launch_bounds__(256) void sim_kernel(float* __restrict__ out)
{
    const int b    = blockIdx.x * 8 + (threadIdx.x >> 5);
    const int lane = threadIdx.x & 31;
    const float* s1 = out + (size_t)b * NFEAT;
    const float* s2 = out + (size_t)(NBATCH + b) * NFEAT;
    float dot = 0.f, q1 = 0.f, q2 = 0.f;
    for (int j = lane; j < NFEAT; j += 32) {
        float a = s1[j], c = s2[j];
        dot += a * c;
        q1  += a * a;
        q2  += c * c;
    }
#pragma unroll
    for (int o = 16; o > 0; o >>= 1) {
        dot += __shfl_xor_sync(0xffffffffu, dot, o);
        q1  += __shfl_xor_sync(0xffffffffu, q1,  o);
        q2  += __shfl_xor_sync(0xffffffffu, q2,  o);
    }
    if (lane == 0) {
        float n1 = sqrtf(fmaxf(q1, 1e-12f));
        float n2 = sqrtf(fmaxf(q2, 1e-12f));
        out[(size_t)NROWS * NFEAT + b] = dot / (n1 * n2);
    }
}

// ---------------- launch -------------------------------------------------
extern "C" void kernel_launch(void* const* d_in, const int* in_sizes, int n_in,
                              void* d_out, int out_size)
{
    (void)in_sizes; (void)n_in; (void)out_size;
    const int*   ids1 = (const int*)  d_in[0];
    const int*   ids2 = (const int*)  d_in[1];
    const float* emb  = (const float*)d_in[2];
    const float* W    = (const float*)d_in[3];
    const float* U    = (const float*)d_in[4];
    const float* bias = (const float*)d_in[5];
    float* out = (float*)d_out;

    cudaFuncSetAttribute(rnn_kernel,
                         cudaFuncAttributeMaxDynamicSharedMemorySize,
                         SM_TOTAL_BYTES);

    dim3 g1(NFEAT / 128, (VOCAB1 + 127) / 128);   // 4 x 391
    ew_kernel<<<g1, 256>>>(emb, W);
    rnn_kernel<<<NROWS / 16, 256, SM_TOTAL_BYTES>>>(ids1, ids2, U, bias, out);
    sim_kernel<<<NBATCH / 8, 256>>>(out);
}

// round 7
// speedup vs baseline: 1.6326x; 1.0298x over previous
#include <cuda_runtime.h>
#include <cuda_fp16.h>
#include <math.h>

#define VOCAB1 50001
#define NEMB   256
#define NSEQ   64
#define NFEAT  512
#define NBATCH 1024
#define NROWS  2048

typedef unsigned long long ull;

// ---------------- device scratch ----------------
__device__ float  g_EW[(size_t)VOCAB1 * NFEAT];   // ~102 MB projected embeddings
__device__ __half g_U16[16 * 32768];              // U fp16 hi/lo, 16 k-chunks, swizzled

// ---------------- packed f32x2 helpers (scalar ew) ----------------
__device__ __forceinline__ ull pk2(float lo, float hi) {
    ull r; asm("mov.b64 %0, {%1, %2};" : "=l"(r) : "f"(lo), "f"(hi)); return r;
}
__device__ __forceinline__ void upk2(ull v, float &lo, float &hi) {
    asm("mov.b64 {%0, %1}, %2;" : "=f"(lo), "=f"(hi) : "l"(v));
}
__device__ __forceinline__ ull fma2(ull a, ull b, ull c) {
    ull d; asm("fma.rn.f32x2 %0, %1, %2, %3;" : "=l"(d) : "l"(a), "l"(b), "l"(c)); return d;
}

// ---------------- common helpers ----------------
__device__ __forceinline__ unsigned smem_u32(const void* p) {
    unsigned a;
    asm("{ .reg .u64 t; cvta.to.shared.u64 t, %1; cvt.u32.u64 %0, t; }" : "=r"(a) : "l"(p));
    return a;
}
__device__ __forceinline__ void mbar_init(unsigned a, unsigned cnt) {
    asm volatile("mbarrier.init.shared.b64 [%0], %1;" :: "r"(a), "r"(cnt) : "memory");
}
__device__ __forceinline__ void mbar_wait(unsigned a, unsigned par) {
    asm volatile(
        "{\n\t.reg .pred P;\n\t"
        "WL_%=:\n\t"
        "mbarrier.try_wait.parity.acquire.cta.shared::cta.b64 P, [%0], %1, 0x989680;\n\t"
        "@!P bra WL_%=;\n\t}"
        :: "r"(a), "r"(par) : "memory");
}
__device__ __forceinline__ void bulk_load(unsigned dst, const void* src,
                                          unsigned bytes, unsigned mbar) {
    asm volatile("mbarrier.arrive.expect_tx.shared.b64 _, [%0], %1;"
                 :: "r"(mbar), "r"(bytes) : "memory");
    asm volatile(
        "cp.async.bulk.shared::cta.global.mbarrier::complete_tx::bytes [%0], [%1], %2, [%3];"
        :: "r"(dst), "l"(src), "r"(bytes), "r"(mbar) : "memory");
}

// ---------------- mma.sync / ldmatrix (sm_80 path, valid on sm_100 base) --
__device__ __forceinline__ void ldsm_x4(unsigned &r0, unsigned &r1,
                                        unsigned &r2, unsigned &r3, unsigned addr) {
    asm volatile("ldmatrix.sync.aligned.m8n8.x4.shared.b16 {%0,%1,%2,%3}, [%4];"
                 : "=r"(r0), "=r"(r1), "=r"(r2), "=r"(r3) : "r"(addr));
}
__device__ __forceinline__ void mma16816(float* c,
                                         unsigned a0, unsigned a1, unsigned a2, unsigned a3,
                                         unsigned b0, unsigned b1) {
    asm volatile("mma.sync.aligned.m16n8k16.row.col.f32.f16.f16.f32 "
                 "{%0,%1,%2,%3}, {%4,%5,%6,%7}, {%8,%9}, {%0,%1,%2,%3};"
                 : "+f"(c[0]), "+f"(c[1]), "+f"(c[2]), "+f"(c[3])
                 : "r"(a0), "r"(a1), "r"(a2), "r"(a3), "r"(b0), "r"(b1));
}

// U chunk swizzle: chunk holds [n=512][kk=32] halfs (hi then lo, 16384 each).
// half index = n*32 + (((kk>>3) + (n>>1)) & 3)*8 + (kk&7)  -> ldmatrix conflict-free.
__device__ __forceinline__ int u_hidx(int n, int kk) {
    return n * 32 + (((((kk >> 3) + (n >> 1)) & 3)) << 3) + (kk & 7);
}

// ---------------- prep: U -> fp16 hi/lo swizzled chunks -------------------
__global__ __launch_bounds__(256) void prepU_kernel(const float* __restrict__ U)
{
    int idx = blockIdx.x * 256 + threadIdx.x;
    if (idx < NFEAT * NFEAT) {
        int k = idx >> 9, n = idx & 511;
        float v = U[idx];
        __half hi = __float2half_rn(v);
        __half lo = __float2half_rn(v - __half2float(hi));
        int c = k >> 5, kk = k & 31;
        int h = u_hidx(n, kk);
        g_U16[c * 32768 + h]         = hi;
        g_U16[c * 32768 + 16384 + h] = lo;
    }
}

// ---------------- Kernel 1: EW = embedding @ W (scalar, proven) -----------
__global__ __launch_bounds__(256) void ew_kernel(const float* __restrict__ emb,
                                                 const float* __restrict__ W)
{
    __shared__ __align__(16) float As[16][128];
    __shared__ __align__(16) float Bs[16][128];
    const int bm = blockIdx.y * 128;
    const int bn = blockIdx.x * 128;
    const int tid = threadIdx.x;
    const int tx = tid & 15;
    const int ty = tid >> 4;
    const int m0 = ty * 8;
    const int n0 = tx * 8;
    const int lrA = tid >> 1;
    const int lkA = (tid & 1) * 8;
    const int lkB = ty;
    const int lnB = tx * 8;

    ull acc[8][4];
#pragma unroll
    for (int i = 0; i < 8; i++)
#pragma unroll
        for (int j = 0; j < 4; j++) acc[i][j] = 0ull;

    const int growA = bm + lrA;
    const bool vA = (growA < VOCAB1);

    for (int k0 = 0; k0 < NEMB; k0 += 16) {
        float4 a0 = make_float4(0.f, 0.f, 0.f, 0.f), a1 = a0;
        if (vA) {
            a0 = *(const float4*)(emb + (size_t)growA * NEMB + k0 + lkA);
            a1 = *(const float4*)(emb + (size_t)growA * NEMB + k0 + lkA + 4);
        }
        float4 b0 = *(const float4*)(W + (size_t)(k0 + lkB) * NFEAT + bn + lnB);
        float4 b1 = *(const float4*)(W + (size_t)(k0 + lkB) * NFEAT + bn + lnB + 4);
        __syncthreads();
        As[lkA + 0][lrA] = a0.x; As[lkA + 1][lrA] = a0.y;
        As[lkA + 2][lrA] = a0.z; As[lkA + 3][lrA] = a0.w;
        As[lkA + 4][lrA] = a1.x; As[lkA + 5][lrA] = a1.y;
        As[lkA + 6][lrA] = a1.z; As[lkA + 7][lrA] = a1.w;
        *(float4*)&Bs[lkB][lnB]     = b0;
        *(float4*)&Bs[lkB][lnB + 4] = b1;
        __syncthreads();
#pragma unroll
        for (int k = 0; k < 16; k++) {
            float4 A0 = *(const float4*)&As[k][m0];
            float4 A1 = *(const float4*)&As[k][m0 + 4];
            longlong2 B0 = *(const longlong2*)&Bs[k][n0];
            longlong2 B1 = *(const longlong2*)&Bs[k][n0 + 4];
            ull b01 = (ull)B0.x, b23 = (ull)B0.y, b45 = (ull)B1.x, b67 = (ull)B1.y;
            float av[8] = {A0.x, A0.y, A0.z, A0.w, A1.x, A1.y, A1.z, A1.w};
#pragma unroll
            for (int i = 0; i < 8; i++) {
                ull ad = pk2(av[i], av[i]);
                acc[i][0] = fma2(ad, b01, acc[i][0]);
                acc[i][1] = fma2(ad, b23, acc[i][1]);
                acc[i][2] = fma2(ad, b45, acc[i][2]);
                acc[i][3] = fma2(ad, b67, acc[i][3]);
            }
        }
    }
#pragma unroll
    for (int i = 0; i < 8; i++) {
        int row = bm + m0 + i;
        if (row < VOCAB1) {
            float c0, c1, c2, c3, c4, c5, c6, c7;
            upk2(acc[i][0], c0, c1); upk2(acc[i][1], c2, c3);
            upk2(acc[i][2], c4, c5); upk2(acc[i][3], c6, c7);
            *(float4*)(g_EW + (size_t)row * NFEAT + bn + n0)     = make_float4(c0, c1, c2, c3);
            *(float4*)(g_EW + (size_t)row * NFEAT + bn + n0 + 4) = make_float4(c4, c5, c6, c7);
        }
    }
}

// ---------------- Kernel 2: tensor-core recurrent scan --------------------
// 64 CTAs x 32 rows, 256 threads (8 warps x 64-feature slice).
// h kept in SMEM as fp16 hi/lo ([32][536] each, pad for conflict-free LDSM).
// U streamed fp16 hi/lo via cp.async.bulk double buffer (2 x 64KB).
// 3-term split: Hh*Uh + Hl*Uh + Hh*Ul, fp32 accum in mma.sync.m16n8k16.
#define RS_SID   16
#define RS_U0    1024
#define RS_U1    (RS_U0 + 65536)            // 66560
#define RS_HHI   (RS_U1 + 65536)            // 132096
#define RS_HLO   (RS_HHI + 32 * 536 * 2)    // 166400
#define RS_TOTAL (RS_HLO + 32 * 536 * 2)    // 200704 bytes

__global__ __launch_bounds__(256, 1) void rnn_tensor_kernel(
    const int*  __restrict__ ids1,
    const int*  __restrict__ ids2,
    const float* __restrict__ bias,
    float* __restrict__ out)
{
    extern __shared__ __align__(1024) char rsm[];
    const unsigned smb = smem_u32(rsm);
    const int tid  = threadIdx.x;
    const int wid  = tid >> 5;
    const int lane = tid & 31;
    const int rb0  = blockIdx.x * 32;
    const int* myids = (rb0 < NBATCH) ? ids1 : ids2;
    const int rbase  = rb0 & (NBATCH - 1);

    int* s_id = (int*)(rsm + RS_SID);
    const unsigned mb0 = smb + 0, mb1 = smb + 8;
    const unsigned ubase0 = smb + RS_U0;
    const unsigned ubase1 = smb + RS_U1;
    const unsigned hhi = smb + RS_HHI;
    const unsigned hlo = smb + RS_HLO;
    __half* h_hi = (__half*)(rsm + RS_HHI);
    __half* h_lo = (__half*)(rsm + RS_HLO);

    // zero h (incl. padding)
    for (int i = tid; i < 32 * 536; i += 256) { h_hi[i] = __half(0); h_lo[i] = __half(0); }
    if (tid == 0) { mbar_init(mb0, 1); mbar_init(mb1, 1); }
    __syncthreads();
    if (tid == 0) {
        bulk_load(ubase0, g_U16,          65536, mb0);
        bulk_load(ubase1, g_U16 + 32768,  65536, mb1);
    }

    const int n0w = wid * 64;

    // bias preload (2 cols per n-tile for this lane)
    float2 bias2[8];
#pragma unroll
    for (int nt = 0; nt < 8; nt++)
        bias2[nt] = *(const float2*)(bias + n0w + nt * 8 + (lane & 3) * 2);

    // ldmatrix address components
    const int a_row  = lane & 15;                  // + mt*16
    const int a_koct = (lane >> 4) * 8;            // 0 or 8
    const int b_i    = lane & 7;
    const int b_seg  = lane >> 3;                  // 0..3
    const int b_nadd = (b_seg & 2) ? 8 : 0;
    const int b_kadd = (b_seg & 1) ? 8 : 0;

    unsigned ph0 = 0, ph1 = 0;

    for (int t = 0; t < NSEQ; t++) {
        if (tid < 32) s_id[tid] = myids[(rbase + tid) * NSEQ + t];

        float c[2][8][4];
#pragma unroll
        for (int mt = 0; mt < 2; mt++)
#pragma unroll
            for (int nt = 0; nt < 8; nt++)
#pragma unroll
                for (int q = 0; q < 4; q++) c[mt][nt][q] = 0.f;

#pragma unroll 1
        for (int c2 = 0; c2 < 8; c2++) {
#pragma unroll
            for (int hb = 0; hb < 2; hb++) {
                const int ck = c2 * 2 + hb;
                if (hb) { mbar_wait(mb1, ph1); ph1 ^= 1; }
                else    { mbar_wait(mb0, ph0); ph0 ^= 1; }
                const unsigned ub = hb ? ubase1 : ubase0;
#pragma unroll
                for (int kt = 0; kt < 2; kt++) {
                    // A fragments: h hi/lo, 2 m-tiles
                    const int kglob = ck * 32 + kt * 16 + a_koct;
                    unsigned ah[2][4], al[2][4];
#pragma unroll
                    for (int mt = 0; mt < 2; mt++) {
                        const unsigned aoff =
                            (unsigned)(((a_row + mt * 16) * 536 + kglob) * 2);
                        ldsm_x4(ah[mt][0], ah[mt][1], ah[mt][2], ah[mt][3], hhi + aoff);
                        ldsm_x4(al[mt][0], al[mt][1], al[mt][2], al[mt][3], hlo + aoff);
                    }
                    const int kk = kt * 16 + b_kadd;
#pragma unroll
                    for (int p = 0; p < 4; p++) {
                        const int n = n0w + p * 16 + b_nadd + b_i;
                        const unsigned boff = (unsigned)(u_hidx(n, kk) * 2);
                        unsigned bh0, bh1, bh2, bh3, bl0, bl1, bl2, bl3;
                        ldsm_x4(bh0, bh1, bh2, bh3, ub + boff);
                        ldsm_x4(bl0, bl1, bl2, bl3, ub + 32768 + boff);
#pragma unroll
                        for (int mt = 0; mt < 2; mt++) {
                            mma16816(c[mt][2 * p],     ah[mt][0], ah[mt][1], ah[mt][2], ah[mt][3], bh0, bh1);
                            mma16816(c[mt][2 * p + 1], ah[mt][0], ah[mt][1], ah[mt][2], ah[mt][3], bh2, bh3);
                            mma16816(c[mt][2 * p],     al[mt][0], al[mt][1], al[mt][2], al[mt][3], bh0, bh1);
                            mma16816(c[mt][2 * p + 1], al[mt][0], al[mt][1], al[mt][2], al[mt][3], bh2, bh3);
                            mma16816(c[mt][2 * p],     ah[mt][0], ah[mt][1], ah[mt][2], ah[mt][3], bl0, bl1);
                            mma16816(c[mt][2 * p + 1], ah[mt][0], ah[mt][1], ah[mt][2], ah[mt][3], bl2, bl3);
                        }
                    }
                }
                __syncthreads();   // everyone done with this U buffer
                if (tid == 0) {
                    const int nc = t * 16 + ck + 2;
                    if (nc < NSEQ * 16)
                        bulk_load(hb ? ubase1 : ubase0,
                                  g_U16 + (size_t)(nc & 15) * 32768, 65536,
                                  hb ? mb1 : mb0);
                }
            }
        }

        // epilogue: x gather + bias + tanh + masked h update (hi/lo halves)
#pragma unroll
        for (int mt = 0; mt < 2; mt++) {
            const int r1 = mt * 16 + (lane >> 2);
            const int r2 = r1 + 8;
            const int gid1 = s_id[r1], gid2 = s_id[r2];
            const float* e1 = g_EW + (size_t)gid1 * NFEAT;
            const float* e2 = g_EW + (size_t)gid2 * NFEAT;
            float2 X1[8], X2[8];
#pragma unroll
            for (int nt = 0; nt < 8; nt++) {
                const int col = n0w + nt * 8 + (lane & 3) * 2;
                X1[nt] = *(const float2*)(e1 + col);
                X2[nt] = *(const float2*)(e2 + col);
            }
            const bool m1 = (gid1 != 0), m2 = (gid2 != 0);
#pragma unroll
            for (int nt = 0; nt < 8; nt++) {
                const int col = n0w + nt * 8 + (lane & 3) * 2;
                if (m1) {
                    float v0 = tanhf(c[mt][nt][0] + X1[nt].x + bias2[nt].x);
                    float v1 = tanhf(c[mt][nt][1] + X1[nt].y + bias2[nt].y);
                    __half p0 = __float2half_rn(v0);
                    __half p1 = __float2half_rn(v1);
                    *(__half2*)(h_hi + r1 * 536 + col) = __halves2half2(p0, p1);
                    *(__half2*)(h_lo + r1 * 536 + col) =
                        __halves2half2(__float2half_rn(v0 - __half2float(p0)),
                                       __float2half_rn(v1 - __half2float(p1)));
                }
                if (m2) {
                    float v2 = tanhf(c[mt][nt][2] + X2[nt].x + bias2[nt].x);
                    float v3 = tanhf(c[mt][nt][3] + X2[nt].y + bias2[nt].y);
                    __half p2 = __float2half_rn(v2);
                    __half p3 = __float2half_rn(v3);
                    *(__half2*)(h_hi + r2 * 536 + col) = __halves2half2(p2, p3);
                    *(__half2*)(h_lo + r2 * 536 + col) =
                        __halves2half2(__float2half_rn(v2 - __half2float(p2)),
                                       __float2half_rn(v3 - __half2float(p3)));
                }
            }
        }
        __syncthreads();   // h updates visible before next step's ldmatrix
    }

    // write final states: h = hi + lo
    for (int i = tid; i < 32 * NFEAT; i += 256) {
        const int r = i >> 9, cc = i & 511;
        out[(size_t)(rb0 + r) * NFEAT + cc] =
            __half2float(h_hi[r * 536 + cc]) + __half2float(h_lo[r * 536 + cc]);
    }
}

// ---------------- Kernel 3: cosine similarity ---------------------------
__global__ __launch_bounds__(256) void sim_kernel(float* __restrict__ out)
{
    const int b    = blockIdx.x * 8 + (threadIdx.x >> 5);
    const int lane = threadIdx.x & 31;
    const float* s1 = out + (size_t)b * NFEAT;
    const float* s2 = out + (size_t)(NBATCH + b) * NFEAT;
    float dot = 0.f, q1 = 0.f, q2 = 0.f;
    for (int j = lane; j < NFEAT; j += 32) {
        float a = s1[j], c = s2[j];
        dot += a * c;
        q1  += a * a;
        q2  += c * c;
    }
#pragma unroll
    for (int o = 16; o > 0; o >>= 1) {
        dot += __shfl_xor_sync(0xffffffffu, dot, o);
        q1  += __shfl_xor_sync(0xffffffffu, q1,  o);
        q2  += __shfl_xor_sync(0xffffffffu, q2,  o);
    }
    if (lane == 0) {
        float n1 = sqrtf(fmaxf(q1, 1e-12f));
        float n2 = sqrtf(fmaxf(q2, 1e-12f));
        out[(size_t)NROWS * NFEAT + b] = dot / (n1 * n2);
    }
}

// ---------------- launch -------------------------------------------------
extern "C" void kernel_launch(void* const* d_in, const int* in_sizes, int n_in,
                              void* d_out, int out_size)
{
    (void)in_sizes; (void)n_in; (void)out_size;
    const int*   ids1 = (const int*)  d_in[0];
    const int*   ids2 = (const int*)  d_in[1];
    const float* emb  = (const float*)d_in[2];
    const float* W    = (const float*)d_in[3];
    const float* U    = (const float*)d_in[4];
    const float* bias = (const float*)d_in[5];
    float* out = (float*)d_out;

    cudaFuncSetAttribute(rnn_tensor_kernel,
                         cudaFuncAttributeMaxDynamicSharedMemorySize, RS_TOTAL);

    prepU_kernel<<<(NFEAT * NFEAT + 255) / 256, 256>>>(U);
    dim3 g1(NFEAT / 128, (VOCAB1 + 127) / 128);
    ew_kernel<<<g1, 256>>>(emb, W);
    rnn_tensor_kernel<<<NROWS / 32, 256, RS_TOTAL>>>(ids1, ids2, bias, out);
    sim_kernel<<<NBATCH / 8, 256>>>(out);
}

// round 10
// speedup vs baseline: 2.6029x; 1.5943x over previous
#include <cuda_runtime.h>
#include <cuda_fp16.h>
#include <math.h>

#define VOCAB1 50001
#define NEMB   256
#define NSEQ   64
#define NFEAT  512
#define NBATCH 1024
#define NROWS  2048

typedef unsigned long long ull;

// ---------------- device scratch ----------------
__device__ float  g_EW[(size_t)VOCAB1 * NFEAT];   // ~102 MB projected embeddings
__device__ __half g_U16[16 * 32768];              // U fp16 hi/lo, 16 k-chunks, swizzled

// ---------------- packed f32x2 helpers (scalar ew) ----------------
__device__ __forceinline__ ull pk2(float lo, float hi) {
    ull r; asm("mov.b64 %0, {%1, %2};" : "=l"(r) : "f"(lo), "f"(hi)); return r;
}
__device__ __forceinline__ void upk2(ull v, float &lo, float &hi) {
    asm("mov.b64 {%0, %1}, %2;" : "=f"(lo), "=f"(hi) : "l"(v));
}
__device__ __forceinline__ ull fma2(ull a, ull b, ull c) {
    ull d; asm("fma.rn.f32x2 %0, %1, %2, %3;" : "=l"(d) : "l"(a), "l"(b), "l"(c)); return d;
}

// ---------------- common helpers ----------------
__device__ __forceinline__ unsigned smem_u32(const void* p) {
    unsigned a;
    asm("{ .reg .u64 t; cvta.to.shared.u64 t, %1; cvt.u32.u64 %0, t; }" : "=r"(a) : "l"(p));
    return a;
}
__device__ __forceinline__ void mbar_init(unsigned a, unsigned cnt) {
    asm volatile("mbarrier.init.shared.b64 [%0], %1;" :: "r"(a), "r"(cnt) : "memory");
}
__device__ __forceinline__ void mbar_wait(unsigned a, unsigned par) {
    asm volatile(
        "{\n\t.reg .pred P;\n\t"
        "WL_%=:\n\t"
        "mbarrier.try_wait.parity.acquire.cta.shared::cta.b64 P, [%0], %1, 0x989680;\n\t"
        "@!P bra WL_%=;\n\t}"
        :: "r"(a), "r"(par) : "memory");
}
__device__ __forceinline__ void bulk_load(unsigned dst, const void* src,
                                          unsigned bytes, unsigned mbar) {
    asm volatile("mbarrier.arrive.expect_tx.shared.b64 _, [%0], %1;"
                 :: "r"(mbar), "r"(bytes) : "memory");
    asm volatile(
        "cp.async.bulk.shared::cta.global.mbarrier::complete_tx::bytes [%0], [%1], %2, [%3];"
        :: "r"(dst), "l"(src), "r"(bytes), "r"(mbar) : "memory");
}

// ---------------- mma.sync / ldmatrix -------------------------------------
__device__ __forceinline__ void ldsm_x4(unsigned &r0, unsigned &r1,
                                        unsigned &r2, unsigned &r3, unsigned addr) {
    asm volatile("ldmatrix.sync.aligned.m8n8.x4.shared.b16 {%0,%1,%2,%3}, [%4];"
                 : "=r"(r0), "=r"(r1), "=r"(r2), "=r"(r3) : "r"(addr));
}
__device__ __forceinline__ void mma16816(float* c,
                                         unsigned a0, unsigned a1, unsigned a2, unsigned a3,
                                         unsigned b0, unsigned b1) {
    asm volatile("mma.sync.aligned.m16n8k16.row.col.f32.f16.f16.f32 "
                 "{%0,%1,%2,%3}, {%4,%5,%6,%7}, {%8,%9}, {%0,%1,%2,%3};"
                 : "+f"(c[0]), "+f"(c[1]), "+f"(c[2]), "+f"(c[3])
                 : "r"(a0), "r"(a1), "r"(a2), "r"(a3), "r"(b0), "r"(b1));
}

// U chunk swizzle: chunk holds [n=512][kk=32] halfs (hi then lo, 16384 each).
__device__ __forceinline__ int u_hidx(int n, int kk) {
    return n * 32 + (((((kk >> 3) + (n >> 1)) & 3)) << 3) + (kk & 7);
}

// ---------------- prep: U -> fp16 hi/lo swizzled chunks -------------------
__global__ __launch_bounds__(256) void prepU_kernel(const float* __restrict__ U)
{
    int idx = blockIdx.x * 256 + threadIdx.x;
    if (idx < NFEAT * NFEAT) {
        int k = idx >> 9, n = idx & 511;
        float v = U[idx];
        __half hi = __float2half_rn(v);
        __half lo = __float2half_rn(v - __half2float(hi));
        int c = k >> 5, kk = k & 31;
        int h = u_hidx(n, kk);
        g_U16[c * 32768 + h]         = hi;
        g_U16[c * 32768 + 16384 + h] = lo;
    }
}

// ---------------- Kernel 1: EW = embedding @ W (scalar, proven) -----------
__global__ __launch_bounds__(256) void ew_kernel(const float* __restrict__ emb,
                                                 const float* __restrict__ W)
{
    __shared__ __align__(16) float As[16][128];
    __shared__ __align__(16) float Bs[16][128];
    const int bm = blockIdx.y * 128;
    const int bn = blockIdx.x * 128;
    const int tid = threadIdx.x;
    const int tx = tid & 15;
    const int ty = tid >> 4;
    const int m0 = ty * 8;
    const int n0 = tx * 8;
    const int lrA = tid >> 1;
    const int lkA = (tid & 1) * 8;
    const int lkB = ty;
    const int lnB = tx * 8;

    ull acc[8][4];
#pragma unroll
    for (int i = 0; i < 8; i++)
#pragma unroll
        for (int j = 0; j < 4; j++) acc[i][j] = 0ull;

    const int growA = bm + lrA;
    const bool vA = (growA < VOCAB1);

    for (int k0 = 0; k0 < NEMB; k0 += 16) {
        float4 a0 = make_float4(0.f, 0.f, 0.f, 0.f), a1 = a0;
        if (vA) {
            a0 = *(const float4*)(emb + (size_t)growA * NEMB + k0 + lkA);
            a1 = *(const float4*)(emb + (size_t)growA * NEMB + k0 + lkA + 4);
        }
        float4 b0 = *(const float4*)(W + (size_t)(k0 + lkB) * NFEAT + bn + lnB);
        float4 b1 = *(const float4*)(W + (size_t)(k0 + lkB) * NFEAT + bn + lnB + 4);
        __syncthreads();
        As[lkA + 0][lrA] = a0.x; As[lkA + 1][lrA] = a0.y;
        As[lkA + 2][lrA] = a0.z; As[lkA + 3][lrA] = a0.w;
        As[lkA + 4][lrA] = a1.x; As[lkA + 5][lrA] = a1.y;
        As[lkA + 6][lrA] = a1.z; As[lkA + 7][lrA] = a1.w;
        *(float4*)&Bs[lkB][lnB]     = b0;
        *(float4*)&Bs[lkB][lnB + 4] = b1;
        __syncthreads();
#pragma unroll
        for (int k = 0; k < 16; k++) {
            float4 A0 = *(const float4*)&As[k][m0];
            float4 A1 = *(const float4*)&As[k][m0 + 4];
            longlong2 B0 = *(const longlong2*)&Bs[k][n0];
            longlong2 B1 = *(const longlong2*)&Bs[k][n0 + 4];
            ull b01 = (ull)B0.x, b23 = (ull)B0.y, b45 = (ull)B1.x, b67 = (ull)B1.y;
            float av[8] = {A0.x, A0.y, A0.z, A0.w, A1.x, A1.y, A1.z, A1.w};
#pragma unroll
            for (int i = 0; i < 8; i++) {
                ull ad = pk2(av[i], av[i]);
                acc[i][0] = fma2(ad, b01, acc[i][0]);
                acc[i][1] = fma2(ad, b23, acc[i][1]);
                acc[i][2] = fma2(ad, b45, acc[i][2]);
                acc[i][3] = fma2(ad, b67, acc[i][3]);
            }
        }
    }
#pragma unroll
    for (int i = 0; i < 8; i++) {
        int row = bm + m0 + i;
        if (row < VOCAB1) {
            float c0, c1, c2, c3, c4, c5, c6, c7;
            upk2(acc[i][0], c0, c1); upk2(acc[i][1], c2, c3);
            upk2(acc[i][2], c4, c5); upk2(acc[i][3], c6, c7);
            *(float4*)(g_EW + (size_t)row * NFEAT + bn + n0)     = make_float4(c0, c1, c2, c3);
            *(float4*)(g_EW + (size_t)row * NFEAT + bn + n0 + 4) = make_float4(c4, c5, c6, c7);
        }
    }
}

// ---------------- Kernel 2: tensor-core recurrent scan --------------------
// 128 CTAs x 16 rows, 256 threads (8 warps x 64-feature slice).
// h in SMEM as fp16 hi/lo ([16][536] each). U streamed hi/lo via
// cp.async.bulk double buffer (2 x 64KB). 3-term split, fp32 accum.
#define RS_SID   16
#define RS_U0    1024
#define RS_U1    (RS_U0 + 65536)            // 66560
#define RS_HHI   (RS_U1 + 65536)            // 132096
#define RS_HLO   (RS_HHI + 16 * 536 * 2)    // 149248
#define RS_TOTAL (RS_HLO + 16 * 536 * 2)    // 166400 bytes

__global__ __launch_bounds__(256, 1) void rnn_tensor_kernel(
    const int*  __restrict__ ids1,
    const int*  __restrict__ ids2,
    const float* __restrict__ bias,
    float* __restrict__ out)
{
    extern __shared__ __align__(1024) char rsm[];
    const unsigned smb = smem_u32(rsm);
    const int tid  = threadIdx.x;
    const int wid  = tid >> 5;
    const int lane = tid & 31;
    const int rb0  = blockIdx.x * 16;
    const int* myids = (rb0 < NBATCH) ? ids1 : ids2;
    const int rbase  = rb0 & (NBATCH - 1);

    int* s_id = (int*)(rsm + RS_SID);
    const unsigned mb0 = smb + 0, mb1 = smb + 8;
    const unsigned ubase0 = smb + RS_U0;
    const unsigned ubase1 = smb + RS_U1;
    const unsigned hhi = smb + RS_HHI;
    const unsigned hlo = smb + RS_HLO;
    __half* h_hi = (__half*)(rsm + RS_HHI);
    __half* h_lo = (__half*)(rsm + RS_HLO);

    for (int i = tid; i < 16 * 536; i += 256) { h_hi[i] = __half(0); h_lo[i] = __half(0); }
    if (tid == 0) { mbar_init(mb0, 1); mbar_init(mb1, 1); }
    __syncthreads();
    if (tid == 0) {
        bulk_load(ubase0, g_U16,          65536, mb0);
        bulk_load(ubase1, g_U16 + 32768,  65536, mb1);
    }

    const int n0w = wid * 64;

    float2 bias2[8];
#pragma unroll
    for (int nt = 0; nt < 8; nt++)
        bias2[nt] = *(const float2*)(bias + n0w + nt * 8 + (lane & 3) * 2);

    const int a_row  = lane & 15;
    const int a_koct = (lane >> 4) * 8;
    const int b_i    = lane & 7;
    const int b_seg  = lane >> 3;
    const int b_nadd = (b_seg & 2) ? 8 : 0;
    const int b_kadd = (b_seg & 1) ? 8 : 0;

    unsigned ph0 = 0, ph1 = 0;

    for (int t = 0; t < NSEQ; t++) {
        if (tid < 16) s_id[tid] = myids[(rbase + tid) * NSEQ + t];

        float c[8][4];
#pragma unroll
        for (int nt = 0; nt < 8; nt++)
#pragma unroll
            for (int q = 0; q < 4; q++) c[nt][q] = 0.f;

#pragma unroll 1
        for (int c2 = 0; c2 < 8; c2++) {
#pragma unroll
            for (int hb = 0; hb < 2; hb++) {
                const int ck = c2 * 2 + hb;
                if (hb) { mbar_wait(mb1, ph1); ph1 ^= 1; }
                else    { mbar_wait(mb0, ph0); ph0 ^= 1; }
                const unsigned ub = hb ? ubase1 : ubase0;
#pragma unroll
                for (int kt = 0; kt < 2; kt++) {
                    const int kglob = ck * 32 + kt * 16 + a_koct;
                    unsigned ah[4], al[4];
                    const unsigned aoff = (unsigned)((a_row * 536 + kglob) * 2);
                    ldsm_x4(ah[0], ah[1], ah[2], ah[3], hhi + aoff);
                    ldsm_x4(al[0], al[1], al[2], al[3], hlo + aoff);
                    const int kk = kt * 16 + b_kadd;
#pragma unroll
                    for (int p = 0; p < 4; p++) {
                        const int n = n0w + p * 16 + b_nadd + b_i;
                        const unsigned boff = (unsigned)(u_hidx(n, kk) * 2);
                        unsigned bh0, bh1, bh2, bh3, bl0, bl1, bl2, bl3;
                        ldsm_x4(bh0, bh1, bh2, bh3, ub + boff);
                        ldsm_x4(bl0, bl1, bl2, bl3, ub + 32768 + boff);
                        mma16816(c[2 * p],     ah[0], ah[1], ah[2], ah[3], bh0, bh1);
                        mma16816(c[2 * p + 1], ah[0], ah[1], ah[2], ah[3], bh2, bh3);
                        mma16816(c[2 * p],     al[0], al[1], al[2], al[3], bh0, bh1);
                        mma16816(c[2 * p + 1], al[0], al[1], al[2], al[3], bh2, bh3);
                        mma16816(c[2 * p],     ah[0], ah[1], ah[2], ah[3], bl0, bl1);
                        mma16816(c[2 * p + 1], ah[0], ah[1], ah[2], ah[3], bl2, bl3);
                    }
                }
                __syncthreads();   // everyone done with this U buffer
                if (tid == 0) {
                    const int nc = t * 16 + ck + 2;
                    if (nc < NSEQ * 16)
                        bulk_load(hb ? ubase1 : ubase0,
                                  g_U16 + (size_t)(nc & 15) * 32768, 65536,
                                  hb ? mb1 : mb0);
                }
            }
        }

        // epilogue: x gather + bias + tanh + masked h update
        {
            const int r1 = lane >> 2;
            const int r2 = r1 + 8;
            const int gid1 = s_id[r1], gid2 = s_id[r2];
            const float* e1 = g_EW + (size_t)gid1 * NFEAT;
            const float* e2 = g_EW + (size_t)gid2 * NFEAT;
            float2 X1[8], X2[8];
#pragma unroll
            for (int nt = 0; nt < 8; nt++) {
                const int col = n0w + nt * 8 + (lane & 3) * 2;
                X1[nt] = *(const float2*)(e1 + col);
                X2[nt] = *(const float2*)(e2 + col);
            }
            const bool m1 = (gid1 != 0), m2 = (gid2 != 0);
#pragma unroll
            for (int nt = 0; nt < 8; nt++) {
                const int col = n0w + nt * 8 + (lane & 3) * 2;
                if (m1) {
                    float v0 = tanhf(c[nt][0] + X1[nt].x + bias2[nt].x);
                    float v1 = tanhf(c[nt][1] + X1[nt].y + bias2[nt].y);
                    __half p0 = __float2half_rn(v0);
                    __half p1 = __float2half_rn(v1);
                    *(__half2*)(h_hi + r1 * 536 + col) = __halves2half2(p0, p1);
                    *(__half2*)(h_lo + r1 * 536 + col) =
                        __halves2half2(__float2half_rn(v0 - __half2float(p0)),
                                       __float2half_rn(v1 - __half2float(p1)));
                }
                if (m2) {
                    float v2 = tanhf(c[nt][2] + X2[nt].x + bias2[nt].x);
                    float v3 = tanhf(c[nt][3] + X2[nt].y + bias2[nt].y);
                    __half p2 = __float2half_rn(v2);
                    __half p3 = __float2half_rn(v3);
                    *(__half2*)(h_hi + r2 * 536 + col) = __halves2half2(p2, p3);
                    *(__half2*)(h_lo + r2 * 536 + col) =
                        __halves2half2(__float2half_rn(v2 - __half2float(p2)),
                                       __float2half_rn(v3 - __half2float(p3)));
                }
            }
        }
        __syncthreads();   // h updates visible before next step's ldmatrix
    }

    // write final states: h = hi + lo
    for (int i = tid; i < 16 * NFEAT; i += 256) {
        const int r = i >> 9, cc = i & 511;
        out[(size_t)(rb0 + r) * NFEAT + cc] =
            __half2float(h_hi[r * 536 + cc]) + __half2float(h_lo[r * 536 + cc]);
    }
}

// ---------------- Kernel 3: cosine similarity ---------------------------
__global__ __launch_bounds__(256) void sim_kernel(float* __restrict__ out)
{
    const int b    = blockIdx.x * 8 + (threadIdx.x >> 5);
    const int lane = threadIdx.x & 31;
    const float* s1 = out + (size_t)b * NFEAT;
    const float* s2 = out + (size_t)(NBATCH + b) * NFEAT;
    float dot = 0.f, q1 = 0.f, q2 = 0.f;
    for (int j = lane; j < NFEAT; j += 32) {
        float a = s1[j], c = s2[j];
        dot += a * c;
        q1  += a * a;
        q2  += c * c;
    }
#pragma unroll
    for (int o = 16; o > 0; o >>= 1) {
        dot += __shfl_xor_sync(0xffffffffu, dot, o);
        q1  += __shfl_xor_sync(0xffffffffu, q1,  o);
        q2  += __shfl_xor_sync(0xffffffffu, q2,  o);
    }
    if (lane == 0) {
        float n1 = sqrtf(fmaxf(q1, 1e-12f));
        float n2 = sqrtf(fmaxf(q2, 1e-12f));
        out[(size_t)NROWS * NFEAT + b] = dot / (n1 * n2);
    }
}

// ---------------- launch -------------------------------------------------
extern "C" void kernel_launch(void* const* d_in, const int* in_sizes, int n_in,
                              void* d_out, int out_size)
{
    (void)in_sizes; (void)n_in; (void)out_size;
    const int*   ids1 = (const int*)  d_in[0];
    const int*   ids2 = (const int*)  d_in[1];
    const float* emb  = (const float*)d_in[2];
    const float* W    = (const float*)d_in[3];
    const float* U    = (const float*)d_in[4];
    const float* bias = (const float*)d_in[5];
    float* out = (float*)d_out;

    cudaFuncSetAttribute(rnn_tensor_kernel,
                         cudaFuncAttributeMaxDynamicSharedMemorySize, RS_TOTAL);

    prepU_kernel<<<(NFEAT * NFEAT + 255) / 256, 256>>>(U);
    dim3 g1(NFEAT / 128, (VOCAB1 + 127) / 128);
    ew_kernel<<<g1, 256>>>(emb, W);
    rnn_tensor_kernel<<<NROWS / 16, 256, RS_TOTAL>>>(ids1, ids2, bias, out);
    sim_kernel<<<NBATCH / 8, 256>>>(out);
}

// round 11
// speedup vs baseline: 3.0477x; 1.1709x over previous
#include <cuda_runtime.h>
#include <cuda_fp16.h>
#include <math.h>

#define VOCAB1 50001
#define NEMB   256
#define NSEQ   64
#define NFEAT  512
#define NBATCH 1024
#define NROWS  2048

#define NTILES 392                 // ceil(50001/128)
#define VPAD   (NTILES * 128)      // 50176
#define A_PITCH 264                // halfs per padded A row (528B, conflict-free)
#define A_TILE_HALFS (128 * A_PITCH)   // 33792
#define A_TILE_BYTES (A_TILE_HALFS * 2)// 67584

typedef unsigned long long ull;

// ---------------- device scratch ----------------
__device__ float  g_EW[(size_t)VPAD * NFEAT];       // ~103 MB projected embeddings
__device__ __half g_U16[16 * 32768];                // U fp16 hi/lo, 16 k-chunks, swizzled
__device__ __half g_Ah[(size_t)NTILES * A_TILE_HALFS]; // emb hi, padded tiles
__device__ __half g_Al[(size_t)NTILES * A_TILE_HALFS]; // emb lo
__device__ __half g_W16[8 * 32768];                 // W hi/lo, 8 n-slices x (hi 16384 + lo 16384)

// ---------------- common helpers ----------------
__device__ __forceinline__ unsigned smem_u32(const void* p) {
    unsigned a;
    asm("{ .reg .u64 t; cvta.to.shared.u64 t, %1; cvt.u32.u64 %0, t; }" : "=r"(a) : "l"(p));
    return a;
}
__device__ __forceinline__ void mbar_init(unsigned a, unsigned cnt) {
    asm volatile("mbarrier.init.shared.b64 [%0], %1;" :: "r"(a), "r"(cnt) : "memory");
}
__device__ __forceinline__ void mbar_wait(unsigned a, unsigned par) {
    asm volatile(
        "{\n\t.reg .pred P;\n\t"
        "WL_%=:\n\t"
        "mbarrier.try_wait.parity.acquire.cta.shared::cta.b64 P, [%0], %1, 0x989680;\n\t"
        "@!P bra WL_%=;\n\t}"
        :: "r"(a), "r"(par) : "memory");
}
__device__ __forceinline__ void mbar_expect(unsigned a, unsigned bytes) {
    asm volatile("mbarrier.arrive.expect_tx.shared.b64 _, [%0], %1;"
                 :: "r"(a), "r"(bytes) : "memory");
}
__device__ __forceinline__ void raw_bulk(unsigned dst, const void* src,
                                         unsigned bytes, unsigned mbar) {
    asm volatile(
        "cp.async.bulk.shared::cta.global.mbarrier::complete_tx::bytes [%0], [%1], %2, [%3];"
        :: "r"(dst), "l"(src), "r"(bytes), "r"(mbar) : "memory");
}
__device__ __forceinline__ void bulk_load(unsigned dst, const void* src,
                                          unsigned bytes, unsigned mbar) {
    mbar_expect(mbar, bytes);
    raw_bulk(dst, src, bytes, mbar);
}

// ---------------- mma.sync / ldmatrix -------------------------------------
__device__ __forceinline__ void ldsm_x4(unsigned &r0, unsigned &r1,
                                        unsigned &r2, unsigned &r3, unsigned addr) {
    asm volatile("ldmatrix.sync.aligned.m8n8.x4.shared.b16 {%0,%1,%2,%3}, [%4];"
                 : "=r"(r0), "=r"(r1), "=r"(r2), "=r"(r3) : "r"(addr));
}
__device__ __forceinline__ void mma16816(float* c,
                                         unsigned a0, unsigned a1, unsigned a2, unsigned a3,
                                         unsigned b0, unsigned b1) {
    asm volatile("mma.sync.aligned.m16n8k16.row.col.f32.f16.f16.f32 "
                 "{%0,%1,%2,%3}, {%4,%5,%6,%7}, {%8,%9}, {%0,%1,%2,%3};"
                 : "+f"(c[0]), "+f"(c[1]), "+f"(c[2]), "+f"(c[3])
                 : "r"(a0), "r"(a1), "r"(a2), "r"(a3), "r"(b0), "r"(b1));
}

// U chunk swizzle (n=512 rows of 32 kk)
__device__ __forceinline__ int u_hidx(int n, int kk) {
    return n * 32 + (((((kk >> 3) + (n >> 1)) & 3)) << 3) + (kk & 7);
}
// W slice swizzle (nl in [0,64), same rotation trick)
__device__ __forceinline__ int w_hidx(int nl, int kk) {
    return nl * 32 + (((((kk >> 3) + (nl >> 1)) & 3)) << 3) + (kk & 7);
}

// ---------------- prep: U -> fp16 hi/lo swizzled chunks -------------------
__global__ __launch_bounds__(256) void prepU_kernel(const float* __restrict__ U)
{
    int idx = blockIdx.x * 256 + threadIdx.x;
    if (idx < NFEAT * NFEAT) {
        int k = idx >> 9, n = idx & 511;
        float v = U[idx];
        __half hi = __float2half_rn(v);
        __half lo = __float2half_rn(v - __half2float(hi));
        int c = k >> 5, kk = k & 31;
        int h = u_hidx(n, kk);
        g_U16[c * 32768 + h]         = hi;
        g_U16[c * 32768 + 16384 + h] = lo;
    }
}

// ---------------- prep: emb -> fp16 hi/lo padded tiles --------------------
__global__ __launch_bounds__(256) void prepA_kernel(const float* __restrict__ emb)
{
    const int t = blockIdx.x;
    const size_t base = (size_t)t * A_TILE_HALFS;
    for (int idx = threadIdx.x; idx < A_TILE_HALFS; idx += 256) {
        int r = idx / A_PITCH, k = idx % A_PITCH;
        int grow = t * 128 + r;
        float v = (k < NEMB && grow < VOCAB1) ? emb[(size_t)grow * NEMB + k] : 0.f;
        __half hi = __float2half_rn(v);
        __half lo = __float2half_rn(v - __half2float(hi));
        g_Ah[base + idx] = hi;
        g_Al[base + idx] = lo;
    }
}

// ---------------- prep: W -> fp16 hi/lo sliced/swizzled -------------------
__global__ __launch_bounds__(256) void prepW_kernel(const float* __restrict__ W)
{
    int idx = blockIdx.x * 256 + threadIdx.x;
    if (idx < NEMB * NFEAT) {
        int k = idx >> 9, n = idx & 511;          // W[k][n]
        float v = W[idx];
        __half hi = __float2half_rn(v);
        __half lo = __float2half_rn(v - __half2float(hi));
        int j = n >> 6, nl = n & 63;
        int c = k >> 5, kk = k & 31;
        int h = c * 2048 + w_hidx(nl, kk);
        g_W16[j * 32768 + h]         = hi;
        g_W16[j * 32768 + 16384 + h] = lo;
    }
}

// ---------------- Kernel 1: EW = emb @ W via mma.sync ---------------------
// grid (8 n-slices, 392 row-tiles), 256 threads. Everything resident:
// A tile hi/lo (132KB, pitch 264) + B slice (64KB). Warp w: rows 16w..16w+15,
// all 64 slice cols. 3-term split, fp32 accum.
#define EW_MB    8
#define EW_A_HI  1024
#define EW_A_LO  (EW_A_HI + A_TILE_BYTES)   // 68608
#define EW_B     (EW_A_LO + A_TILE_BYTES)   // 136192
#define EW_TOTAL (EW_B + 65536)             // 201728

__global__ __launch_bounds__(256, 1) void ew_mma_kernel()
{
    extern __shared__ __align__(1024) char esm[];
    const unsigned smb = smem_u32(esm);
    const int tid  = threadIdx.x;
    const int wid  = tid >> 5;
    const int lane = tid & 31;
    const int slice = blockIdx.x;
    const int tile  = blockIdx.y;
    const unsigned mb = smb + EW_MB;

    if (tid == 0) mbar_init(mb, 1);
    __syncthreads();
    if (tid == 0) {
        mbar_expect(mb, A_TILE_BYTES * 2 + 65536);
        raw_bulk(smb + EW_A_HI, g_Ah + (size_t)tile * A_TILE_HALFS, A_TILE_BYTES, mb);
        raw_bulk(smb + EW_A_LO, g_Al + (size_t)tile * A_TILE_HALFS, A_TILE_BYTES, mb);
        raw_bulk(smb + EW_B,    g_W16 + (size_t)slice * 32768,      65536,        mb);
    }
    mbar_wait(mb, 0);

    const int a_row  = lane & 15;
    const int a_koct = (lane >> 4) * 8;
    const int b_i    = lane & 7;
    const int b_seg  = lane >> 3;
    const int b_nadd = (b_seg & 2) ? 8 : 0;
    const int b_kadd = (b_seg & 1) ? 8 : 0;

    float c[8][4];
#pragma unroll
    for (int nt = 0; nt < 8; nt++)
#pragma unroll
        for (int q = 0; q < 4; q++) c[nt][q] = 0.f;

#pragma unroll 1
    for (int ck = 0; ck < 8; ck++) {
#pragma unroll
        for (int kt = 0; kt < 2; kt++) {
            const int kglob = ck * 32 + kt * 16 + a_koct;
            const unsigned aoff = (unsigned)(((wid * 16 + a_row) * A_PITCH + kglob) * 2);
            unsigned ah[4], al[4];
            ldsm_x4(ah[0], ah[1], ah[2], ah[3], smb + EW_A_HI + aoff);
            ldsm_x4(al[0], al[1], al[2], al[3], smb + EW_A_LO + aoff);
            const int kk = kt * 16 + b_kadd;
#pragma unroll
            for (int p = 0; p < 4; p++) {
                const int nl = p * 16 + b_nadd + b_i;
                const unsigned boff = (unsigned)((ck * 2048 + w_hidx(nl, kk)) * 2);
                unsigned bh0, bh1, bh2, bh3, bl0, bl1, bl2, bl3;
                ldsm_x4(bh0, bh1, bh2, bh3, smb + EW_B + boff);
                ldsm_x4(bl0, bl1, bl2, bl3, smb + EW_B + 32768 + boff);
                mma16816(c[2 * p],     ah[0], ah[1], ah[2], ah[3], bh0, bh1);
                mma16816(c[2 * p + 1], ah[0], ah[1], ah[2], ah[3], bh2, bh3);
                mma16816(c[2 * p],     al[0], al[1], al[2], al[3], bh0, bh1);
                mma16816(c[2 * p + 1], al[0], al[1], al[2], al[3], bh2, bh3);
                mma16816(c[2 * p],     ah[0], ah[1], ah[2], ah[3], bl0, bl1);
                mma16816(c[2 * p + 1], ah[0], ah[1], ah[2], ah[3], bl2, bl3);
            }
        }
    }

    // write-out (rnn-proven fragment mapping)
    const int grow = tile * 128 + wid * 16;
    const int r1 = lane >> 2;
    const int r2 = r1 + 8;
#pragma unroll
    for (int nt = 0; nt < 8; nt++) {
        const int col = slice * 64 + nt * 8 + (lane & 3) * 2;
        *(float2*)(g_EW + (size_t)(grow + r1) * NFEAT + col) = make_float2(c[nt][0], c[nt][1]);
        *(float2*)(g_EW + (size_t)(grow + r2) * NFEAT + col) = make_float2(c[nt][2], c[nt][3]);
    }
}

// ---------------- Kernel 2: tensor-core recurrent scan (proven R10) -------
#define RS_SID   16
#define RS_U0    1024
#define RS_U1    (RS_U0 + 65536)
#define RS_HHI   (RS_U1 + 65536)
#define RS_HLO   (RS_HHI + 16 * 536 * 2)
#define RS_TOTAL (RS_HLO + 16 * 536 * 2)

__global__ __launch_bounds__(256, 1) void rnn_tensor_kernel(
    const int*  __restrict__ ids1,
    const int*  __restrict__ ids2,
    const float* __restrict__ bias,
    float* __restrict__ out)
{
    extern __shared__ __align__(1024) char rsm[];
    const unsigned smb = smem_u32(rsm);
    const int tid  = threadIdx.x;
    const int wid  = tid >> 5;
    const int lane = tid & 31;
    const int rb0  = blockIdx.x * 16;
    const int* myids = (rb0 < NBATCH) ? ids1 : ids2;
    const int rbase  = rb0 & (NBATCH - 1);

    int* s_id = (int*)(rsm + RS_SID);
    const unsigned mb0 = smb + 0, mb1 = smb + 8;
    const unsigned ubase0 = smb + RS_U0;
    const unsigned ubase1 = smb + RS_U1;
    const unsigned hhi = smb + RS_HHI;
    const unsigned hlo = smb + RS_HLO;
    __half* h_hi = (__half*)(rsm + RS_HHI);
    __half* h_lo = (__half*)(rsm + RS_HLO);

    for (int i = tid; i < 16 * 536; i += 256) { h_hi[i] = __half(0); h_lo[i] = __half(0); }
    if (tid == 0) { mbar_init(mb0, 1); mbar_init(mb1, 1); }
    __syncthreads();
    if (tid == 0) {
        bulk_load(ubase0, g_U16,          65536, mb0);
        bulk_load(ubase1, g_U16 + 32768,  65536, mb1);
    }

    const int n0w = wid * 64;

    float2 bias2[8];
#pragma unroll
    for (int nt = 0; nt < 8; nt++)
        bias2[nt] = *(const float2*)(bias + n0w + nt * 8 + (lane & 3) * 2);

    const int a_row  = lane & 15;
    const int a_koct = (lane >> 4) * 8;
    const int b_i    = lane & 7;
    const int b_seg  = lane >> 3;
    const int b_nadd = (b_seg & 2) ? 8 : 0;
    const int b_kadd = (b_seg & 1) ? 8 : 0;

    unsigned ph0 = 0, ph1 = 0;

    for (int t = 0; t < NSEQ; t++) {
        if (tid < 16) s_id[tid] = myids[(rbase + tid) * NSEQ + t];

        float c[8][4];
#pragma unroll
        for (int nt = 0; nt < 8; nt++)
#pragma unroll
            for (int q = 0; q < 4; q++) c[nt][q] = 0.f;

#pragma unroll 1
        for (int c2 = 0; c2 < 8; c2++) {
#pragma unroll
            for (int hb = 0; hb < 2; hb++) {
                const int ck = c2 * 2 + hb;
                if (hb) { mbar_wait(mb1, ph1); ph1 ^= 1; }
                else    { mbar_wait(mb0, ph0); ph0 ^= 1; }
                const unsigned ub = hb ? ubase1 : ubase0;
#pragma unroll
                for (int kt = 0; kt < 2; kt++) {
                    const int kglob = ck * 32 + kt * 16 + a_koct;
                    unsigned ah[4], al[4];
                    const unsigned aoff = (unsigned)((a_row * 536 + kglob) * 2);
                    ldsm_x4(ah[0], ah[1], ah[2], ah[3], hhi + aoff);
                    ldsm_x4(al[0], al[1], al[2], al[3], hlo + aoff);
                    const int kk = kt * 16 + b_kadd;
#pragma unroll
                    for (int p = 0; p < 4; p++) {
                        const int n = n0w + p * 16 + b_nadd + b_i;
                        const unsigned boff = (unsigned)(u_hidx(n, kk) * 2);
                        unsigned bh0, bh1, bh2, bh3, bl0, bl1, bl2, bl3;
                        ldsm_x4(bh0, bh1, bh2, bh3, ub + boff);
                        ldsm_x4(bl0, bl1, bl2, bl3, ub + 32768 + boff);
                        mma16816(c[2 * p],     ah[0], ah[1], ah[2], ah[3], bh0, bh1);
                        mma16816(c[2 * p + 1], ah[0], ah[1], ah[2], ah[3], bh2, bh3);
                        mma16816(c[2 * p],     al[0], al[1], al[2], al[3], bh0, bh1);
                        mma16816(c[2 * p + 1], al[0], al[1], al[2], al[3], bh2, bh3);
                        mma16816(c[2 * p],     ah[0], ah[1], ah[2], ah[3], bl0, bl1);
                        mma16816(c[2 * p + 1], ah[0], ah[1], ah[2], ah[3], bl2, bl3);
                    }
                }
                __syncthreads();
                if (tid == 0) {
                    const int nc = t * 16 + ck + 2;
                    if (nc < NSEQ * 16)
                        bulk_load(hb ? ubase1 : ubase0,
                                  g_U16 + (size_t)(nc & 15) * 32768, 65536,
                                  hb ? mb1 : mb0);
                }
            }
        }

        {
            const int r1 = lane >> 2;
            const int r2 = r1 + 8;
            const int gid1 = s_id[r1], gid2 = s_id[r2];
            const float* e1 = g_EW + (size_t)gid1 * NFEAT;
            const float* e2 = g_EW + (size_t)gid2 * NFEAT;
            float2 X1[8], X2[8];
#pragma unroll
            for (int nt = 0; nt < 8; nt++) {
                const int col = n0w + nt * 8 + (lane & 3) * 2;
                X1[nt] = *(const float2*)(e1 + col);
                X2[nt] = *(const float2*)(e2 + col);
            }
            const bool m1 = (gid1 != 0), m2 = (gid2 != 0);
#pragma unroll
            for (int nt = 0; nt < 8; nt++) {
                const int col = n0w + nt * 8 + (lane & 3) * 2;
                if (m1) {
                    float v0 = tanhf(c[nt][0] + X1[nt].x + bias2[nt].x);
                    float v1 = tanhf(c[nt][1] + X1[nt].y + bias2[nt].y);
                    __half p0 = __float2half_rn(v0);
                    __half p1 = __float2half_rn(v1);
                    *(__half2*)(h_hi + r1 * 536 + col) = __halves2half2(p0, p1);
                    *(__half2*)(h_lo + r1 * 536 + col) =
                        __halves2half2(__float2half_rn(v0 - __half2float(p0)),
                                       __float2half_rn(v1 - __half2float(p1)));
                }
                if (m2) {
                    float v2 = tanhf(c[nt][2] + X2[nt].x + bias2[nt].x);
                    float v3 = tanhf(c[nt][3] + X2[nt].y + bias2[nt].y);
                    __half p2 = __float2half_rn(v2);
                    __half p3 = __float2half_rn(v3);
                    *(__half2*)(h_hi + r2 * 536 + col) = __halves2half2(p2, p3);
                    *(__half2*)(h_lo + r2 * 536 + col) =
                        __halves2half2(__float2half_rn(v2 - __half2float(p2)),
                                       __float2half_rn(v3 - __half2float(p3)));
                }
            }
        }
        __syncthreads();
    }

    for (int i = tid; i < 16 * NFEAT; i += 256) {
        const int r = i >> 9, cc = i & 511;
        out[(size_t)(rb0 + r) * NFEAT + cc] =
            __half2float(h_hi[r * 536 + cc]) + __half2float(h_lo[r * 536 + cc]);
    }
}

// ---------------- Kernel 3: cosine similarity ---------------------------
__global__ __launch_bounds__(256) void sim_kernel(float* __restrict__ out)
{
    const int b    = blockIdx.x * 8 + (threadIdx.x >> 5);
    const int lane = threadIdx.x & 31;
    const float* s1 = out + (size_t)b * NFEAT;
    const float* s2 = out + (size_t)(NBATCH + b) * NFEAT;
    float dot = 0.f, q1 = 0.f, q2 = 0.f;
    for (int j = lane; j < NFEAT; j += 32) {
        float a = s1[j], c = s2[j];
        dot += a * c;
        q1  += a * a;
        q2  += c * c;
    }
#pragma unroll
    for (int o = 16; o > 0; o >>= 1) {
        dot += __shfl_xor_sync(0xffffffffu, dot, o);
        q1  += __shfl_xor_sync(0xffffffffu, q1,  o);
        q2  += __shfl_xor_sync(0xffffffffu, q2,  o);
    }
    if (lane == 0) {
        float n1 = sqrtf(fmaxf(q1, 1e-12f));
        float n2 = sqrtf(fmaxf(q2, 1e-12f));
        out[(size_t)NROWS * NFEAT + b] = dot / (n1 * n2);
    }
}

// ---------------- launch -------------------------------------------------
extern "C" void kernel_launch(void* const* d_in, const int* in_sizes, int n_in,
                              void* d_out, int out_size)
{
    (void)in_sizes; (void)n_in; (void)out_size;
    const int*   ids1 = (const int*)  d_in[0];
    const int*   ids2 = (const int*)  d_in[1];
    const float* emb  = (const float*)d_in[2];
    const float* W    = (const float*)d_in[3];
    const float* U    = (const float*)d_in[4];
    const float* bias = (const float*)d_in[5];
    float* out = (float*)d_out;

    cudaFuncSetAttribute(ew_mma_kernel,
                         cudaFuncAttributeMaxDynamicSharedMemorySize, EW_TOTAL);
    cudaFuncSetAttribute(rnn_tensor_kernel,
                         cudaFuncAttributeMaxDynamicSharedMemorySize, RS_TOTAL);

    prepU_kernel<<<(NFEAT * NFEAT + 255) / 256, 256>>>(U);
    prepA_kernel<<<NTILES, 256>>>(emb);
    prepW_kernel<<<(NEMB * NFEAT + 255) / 256, 256>>>(W);
    dim3 gew(8, NTILES);
    ew_mma_kernel<<<gew, 256, EW_TOTAL>>>();
    rnn_tensor_kernel<<<NROWS / 16, 256, RS_TOTAL>>>(ids1, ids2, bias, out);
    sim_kernel<<<NBATCH / 8, 256>>>(out);
}